// round 2
// baseline (speedup 1.0000x reference)
#include <cuda_runtime.h>

// Problem shape (fixed by the dataset):
//   pred_boxes: [16, 900, 4] fp32 (cxcywh)  -> 14400 preds
//   gt_boxes:   [1600, 4]    fp32 (cxcywh)
//   out:        [16, 900, 1600] fp32 cost = 5*L1 - 2*GIoU
#define MGT    1600
#define COLS4  (MGT / 4)            // 400 float4 columns per pred row
#define NPRED  (16 * 900)           // 14400
#define PPT    4                    // preds per thread (GT-load amortization)
#define NGRP   (NPRED / PPT)        // 3600 pred groups
#define TOTTH  (NGRP * COLS4)       // 1,440,000 threads
#define TPB    128                  // TOTTH / TPB = 11250 blocks, exact

// GT-derived SoA table: rows = {cx, cy, w, h, x0, y0, x1, y1, area}
__device__ __align__(16) float g_gt[9][MGT];

__global__ void gt_pre_kernel(const float* __restrict__ gt) {
    int i = blockIdx.x * blockDim.x + threadIdx.x;
    if (i < MGT) {
        float4 b = reinterpret_cast<const float4*>(gt)[i];
        float x0 = b.x - 0.5f * b.z;
        float y0 = b.y - 0.5f * b.w;
        float x1 = b.x + 0.5f * b.z;
        float y1 = b.y + 0.5f * b.w;
        g_gt[0][i] = b.x;
        g_gt[1][i] = b.y;
        g_gt[2][i] = b.z;
        g_gt[3][i] = b.w;
        g_gt[4][i] = x0;
        g_gt[5][i] = y0;
        g_gt[6][i] = x1;
        g_gt[7][i] = y1;
        g_gt[8][i] = (x1 - x0) * (y1 - y0);
    }
}

// cost = 5*L1 + 2 - 2*(inter/uni) - 2*(uni/ea)
// (from giou = inter/uni - (ea-uni)/ea = inter/uni - 1 + uni/ea)
__device__ __forceinline__ float cost_one(
    float pcx, float pcy, float pw, float ph,
    float px0, float py0, float px1, float py1, float pa,
    float gcx, float gcy, float gw, float gh,
    float gx0, float gy0, float gx1, float gy1, float ga)
{
    float l1 = fabsf(pcx - gcx) + fabsf(pcy - gcy) + fabsf(pw - gw) + fabsf(ph - gh);

    // Intersection
    float iw = fminf(px1, gx1) - fmaxf(px0, gx0);
    float ih = fminf(py1, gy1) - fmaxf(py0, gy0);
    iw = fmaxf(iw, 0.0f);
    ih = fmaxf(ih, 0.0f);
    float inter = iw * ih;

    float uni = pa + ga - inter;

    // Enclosing box area (max-min >= 0 always, no clip needed)
    float ew = fmaxf(px1, gx1) - fminf(px0, gx0);
    float eh = fmaxf(py1, gy1) - fminf(py0, gy0);
    float ea = ew * eh;

    float iou  = inter * __frcp_rn(uni);   // MUFU.RCP + FMUL
    float uea  = uni   * __frcp_rn(ea);

    float t = fmaf(5.0f, l1, 2.0f);
    t = fmaf(-2.0f, iou, t);
    t = fmaf(-2.0f, uea, t);
    return t;
}

__global__ void __launch_bounds__(TPB)
cost_kernel(const float* __restrict__ pred, float* __restrict__ out)
{
    int id = blockIdx.x * TPB + threadIdx.x;
    int pg = id / COLS4;          // pred group (const divisor -> mul/shift)
    int c  = id - pg * COLS4;     // float4 column
    int p0 = pg * PPT;

    // 9 coalesced LDG.128 from the hot GT table — amortized over PPT preds
    float4 gcx = reinterpret_cast<const float4*>(g_gt[0])[c];
    float4 gcy = reinterpret_cast<const float4*>(g_gt[1])[c];
    float4 gw  = reinterpret_cast<const float4*>(g_gt[2])[c];
    float4 gh  = reinterpret_cast<const float4*>(g_gt[3])[c];
    float4 gx0 = reinterpret_cast<const float4*>(g_gt[4])[c];
    float4 gy0 = reinterpret_cast<const float4*>(g_gt[5])[c];
    float4 gx1 = reinterpret_cast<const float4*>(g_gt[6])[c];
    float4 gy1 = reinterpret_cast<const float4*>(g_gt[7])[c];
    float4 ga  = reinterpret_cast<const float4*>(g_gt[8])[c];

    #pragma unroll
    for (int k = 0; k < PPT; ++k) {
        int p = p0 + k;
        // Pred box: identical address across the warp -> broadcast load
        float4 pb = reinterpret_cast<const float4*>(pred)[p];
        float px0 = pb.x - 0.5f * pb.z;
        float py0 = pb.y - 0.5f * pb.w;
        float px1 = pb.x + 0.5f * pb.z;
        float py1 = pb.y + 0.5f * pb.w;
        float pa  = pb.z * pb.w;

        float4 res;
        res.x = cost_one(pb.x, pb.y, pb.z, pb.w, px0, py0, px1, py1, pa,
                         gcx.x, gcy.x, gw.x, gh.x, gx0.x, gy0.x, gx1.x, gy1.x, ga.x);
        res.y = cost_one(pb.x, pb.y, pb.z, pb.w, px0, py0, px1, py1, pa,
                         gcx.y, gcy.y, gw.y, gh.y, gx0.y, gy0.y, gx1.y, gy1.y, ga.y);
        res.z = cost_one(pb.x, pb.y, pb.z, pb.w, px0, py0, px1, py1, pa,
                         gcx.z, gcy.z, gw.z, gh.z, gx0.z, gy0.z, gx1.z, gy1.z, ga.z);
        res.w = cost_one(pb.x, pb.y, pb.z, pb.w, px0, py0, px1, py1, pa,
                         gcx.w, gcy.w, gw.w, gh.w, gx0.w, gy0.w, gx1.w, gy1.w, ga.w);

        reinterpret_cast<float4*>(out)[p * COLS4 + c] = res;
    }
}

extern "C" void kernel_launch(void* const* d_in, const int* in_sizes, int n_in,
                              void* d_out, int out_size)
{
    (void)in_sizes; (void)n_in; (void)out_size;
    const float* pred = (const float*)d_in[0];
    const float* gt   = (const float*)d_in[1];
    float* out        = (float*)d_out;

    gt_pre_kernel<<<(MGT + TPB - 1) / TPB, TPB>>>(gt);
    cost_kernel<<<TOTTH / TPB, TPB>>>(pred, out);
}

// round 3
// speedup vs baseline: 1.0756x; 1.0756x over previous
#include <cuda_runtime.h>

// Problem shape (fixed by the dataset):
//   pred_boxes: [16, 900, 4] fp32 (cxcywh)  -> 14400 preds
//   gt_boxes:   [1600, 4]    fp32 (cxcywh)
//   out:        [16, 900, 1600] fp32 cost = 5*L1 - 2*GIoU
#define MGT    1600
#define COLS4  (MGT / 4)            // 400 float4 columns per pred row
#define NPRED  (16 * 900)           // 14400
#define PPT    4                    // preds per thread (GT-load amortization)
#define NGRP   (NPRED / PPT)        // 3600 pred groups
#define TOTTH  (NGRP * COLS4)       // 1,440,000 threads
#define TPB    256                  // TOTTH / TPB = 5625 blocks, exact

// ---- rt=1 FFMA-imm helpers (SASS: FFMA R, R, IMM, R issues every cycle
//      on the fma pipe vs every 2 cycles for FADD / 3-reg FFMA) ----
__device__ __forceinline__ float f_add(float a, float b) {          // a + b
    float d; asm("fma.rn.f32 %0, %1, 0f3F800000, %2;" : "=f"(d) : "f"(a), "f"(b)); return d;
}
__device__ __forceinline__ float f_sub(float a, float b) {          // a - b
    float d; asm("fma.rn.f32 %0, %1, 0fBF800000, %2;" : "=f"(d) : "f"(b), "f"(a)); return d;
}
__device__ __forceinline__ float f_fma5(float a, float b) {         // 5*a + b
    float d; asm("fma.rn.f32 %0, %1, 0f40A00000, %2;" : "=f"(d) : "f"(a), "f"(b)); return d;
}
__device__ __forceinline__ float f_fman2(float a, float b) {        // -2*a + b
    float d; asm("fma.rn.f32 %0, %1, 0fC0000000, %2;" : "=f"(d) : "f"(a), "f"(b)); return d;
}
__device__ __forceinline__ float f_rcp(float a) {                   // MUFU.RCP only
    float d; asm("rcp.approx.f32 %0, %1;" : "=f"(d) : "f"(a)); return d;
}

// GT-derived SoA table: rows = {cx, cy, w, h, x0, y0, x1, y1, area}
__device__ __align__(16) float g_gt[9][MGT];

__global__ void gt_pre_kernel(const float* __restrict__ gt) {
    int i = blockIdx.x * blockDim.x + threadIdx.x;
    if (i < MGT) {
        float4 b = reinterpret_cast<const float4*>(gt)[i];
        float x0 = b.x - 0.5f * b.z;
        float y0 = b.y - 0.5f * b.w;
        float x1 = b.x + 0.5f * b.z;
        float y1 = b.y + 0.5f * b.w;
        g_gt[0][i] = b.x;
        g_gt[1][i] = b.y;
        g_gt[2][i] = b.z;
        g_gt[3][i] = b.w;
        g_gt[4][i] = x0;
        g_gt[5][i] = y0;
        g_gt[6][i] = x1;
        g_gt[7][i] = y1;
        g_gt[8][i] = (x1 - x0) * (y1 - y0);
    }
}

// cost = 5*L1 + 2 - 2*(inter/uni) - 2*(uni/ea)
// min/max kept on the ALU pipe (FMNMX) — it has headroom; adds/subs forced
// into rt=1 FFMA-imm forms on the fma pipe.
__device__ __forceinline__ float cost_one(
    float pcx, float pcy, float pw, float ph,
    float px0, float py0, float px1, float py1, float pa, float two,
    float gcx, float gcy, float gw, float gh,
    float gx0, float gy0, float gx1, float gy1, float ga)
{
    // L1 cdist: 4 imm-subs, abs folded into imm-add operand modifiers
    float dcx = f_sub(pcx, gcx);
    float dcy = f_sub(pcy, gcy);
    float dw  = f_sub(pw,  gw);
    float dh  = f_sub(ph,  gh);
    float s1  = f_add(fabsf(dcx), fabsf(dcy));
    float s2  = f_add(fabsf(dw),  fabsf(dh));
    float l1  = f_add(s1, s2);

    // Intersection (FMNMX on alu pipe)
    float iw = f_sub(fminf(px1, gx1), fmaxf(px0, gx0));
    float ih = f_sub(fminf(py1, gy1), fmaxf(py0, gy0));
    iw = fmaxf(iw, 0.0f);
    ih = fmaxf(ih, 0.0f);
    float inter = iw * ih;                         // reg-reg FMUL

    float uni = f_sub(f_add(pa, ga), inter);

    // Enclosing box (max-min >= 0 always)
    float ew = f_sub(fmaxf(px1, gx1), fminf(px0, gx0));
    float eh = f_sub(fmaxf(py1, gy1), fminf(py0, gy0));
    float ea = ew * eh;                            // reg-reg FMUL

    float iou = inter * f_rcp(uni);                // MUFU + FMUL
    float uea = uni   * f_rcp(ea);                 // MUFU + FMUL

    float t = f_fma5(l1, two);                     // 5*l1 + 2
    t = f_fman2(iou, t);                           // -2*iou + t
    t = f_fman2(uea, t);                           // -2*uea + t
    return t;
}

__global__ void __launch_bounds__(TPB)
cost_kernel(const float* __restrict__ pred, float* __restrict__ out)
{
    int id = blockIdx.x * TPB + threadIdx.x;
    int pg = id / COLS4;          // const divisor -> mul/shift
    int c  = id - pg * COLS4;
    int p0 = pg * PPT;
    const float two = 2.0f;

    // 9 coalesced LDG.128 from the hot GT table — amortized over PPT preds
    float4 gcx = reinterpret_cast<const float4*>(g_gt[0])[c];
    float4 gcy = reinterpret_cast<const float4*>(g_gt[1])[c];
    float4 gw  = reinterpret_cast<const float4*>(g_gt[2])[c];
    float4 gh  = reinterpret_cast<const float4*>(g_gt[3])[c];
    float4 gx0 = reinterpret_cast<const float4*>(g_gt[4])[c];
    float4 gy0 = reinterpret_cast<const float4*>(g_gt[5])[c];
    float4 gx1 = reinterpret_cast<const float4*>(g_gt[6])[c];
    float4 gy1 = reinterpret_cast<const float4*>(g_gt[7])[c];
    float4 ga  = reinterpret_cast<const float4*>(g_gt[8])[c];

    #pragma unroll
    for (int k = 0; k < PPT; ++k) {
        int p = p0 + k;
        // Pred box: identical address across the warp -> broadcast load
        float4 pb = reinterpret_cast<const float4*>(pred)[p];
        float px0 = fmaf(-0.5f, pb.z, pb.x);
        float py0 = fmaf(-0.5f, pb.w, pb.y);
        float px1 = fmaf( 0.5f, pb.z, pb.x);
        float py1 = fmaf( 0.5f, pb.w, pb.y);
        float pa  = pb.z * pb.w;

        float4 res;
        res.x = cost_one(pb.x, pb.y, pb.z, pb.w, px0, py0, px1, py1, pa, two,
                         gcx.x, gcy.x, gw.x, gh.x, gx0.x, gy0.x, gx1.x, gy1.x, ga.x);
        res.y = cost_one(pb.x, pb.y, pb.z, pb.w, px0, py0, px1, py1, pa, two,
                         gcx.y, gcy.y, gw.y, gh.y, gx0.y, gy0.y, gx1.y, gy1.y, ga.y);
        res.z = cost_one(pb.x, pb.y, pb.z, pb.w, px0, py0, px1, py1, pa, two,
                         gcx.z, gcy.z, gw.z, gh.z, gx0.z, gy0.z, gx1.z, gy1.z, ga.z);
        res.w = cost_one(pb.x, pb.y, pb.z, pb.w, px0, py0, px1, py1, pa, two,
                         gcx.w, gcy.w, gw.w, gh.w, gx0.w, gy0.w, gx1.w, gy1.w, ga.w);

        reinterpret_cast<float4*>(out)[p * COLS4 + c] = res;
    }
}

extern "C" void kernel_launch(void* const* d_in, const int* in_sizes, int n_in,
                              void* d_out, int out_size)
{
    (void)in_sizes; (void)n_in; (void)out_size;
    const float* pred = (const float*)d_in[0];
    const float* gt   = (const float*)d_in[1];
    float* out        = (float*)d_out;

    gt_pre_kernel<<<(MGT + TPB - 1) / TPB, TPB>>>(gt);
    cost_kernel<<<TOTTH / TPB, TPB>>>(pred, out);
}

// round 4
// speedup vs baseline: 1.2570x; 1.1686x over previous
#include <cuda_runtime.h>

// Problem shape (fixed by the dataset):
//   pred_boxes: [16, 900, 4] fp32 (cxcywh)  -> 14400 preds
//   gt_boxes:   [1600, 4]    fp32 (cxcywh)
//   out:        [16, 900, 1600] fp32 cost = 5*L1 - 2*GIoU
#define MGT    1600
#define COLS4  (MGT / 4)            // 400 float4 columns per pred row
#define NPRED  (16 * 900)           // 14400
#define PPT    4                    // preds per thread
#define NGRP   (NPRED / PPT)        // 3600
#define TOTTH  (NGRP * COLS4)       // 1,440,000 threads
#define TPB    256                  // 5625 blocks, exact

typedef unsigned long long u64;     // a packed f32x2 (register pair)

// ---- f32x2 packed helpers (sm_100a FFMA2 path) ----
__device__ __forceinline__ u64 pk(float lo, float hi) {
    u64 r; asm("mov.b64 %0, {%1, %2};" : "=l"(r) : "f"(lo), "f"(hi)); return r;
}
__device__ __forceinline__ void upk(u64 v, float& lo, float& hi) {
    asm("mov.b64 {%0, %1}, %2;" : "=f"(lo), "=f"(hi) : "l"(v));
}
__device__ __forceinline__ u64 add2(u64 a, u64 b) {
    u64 d; asm("add.rn.f32x2 %0, %1, %2;" : "=l"(d) : "l"(a), "l"(b)); return d;
}
__device__ __forceinline__ u64 mul2(u64 a, u64 b) {
    u64 d; asm("mul.rn.f32x2 %0, %1, %2;" : "=l"(d) : "l"(a), "l"(b)); return d;
}
__device__ __forceinline__ u64 fma2(u64 a, u64 b, u64 c) {
    u64 d; asm("fma.rn.f32x2 %0, %1, %2, %3;" : "=l"(d) : "l"(a), "l"(b), "l"(c)); return d;
}
__device__ __forceinline__ float f_sub(float a, float b) {          // a - b
    float d; asm("fma.rn.f32 %0, %1, 0fBF800000, %2;" : "=f"(d) : "f"(b), "f"(a)); return d;
}
__device__ __forceinline__ float f_rcp(float a) {                   // MUFU.RCP only
    float d; asm("rcp.approx.f32 %0, %1;" : "=f"(d) : "f"(a)); return d;
}

// GT-derived SoA table: rows = {cx, cy, w, h, x0, y0, x1, y1, area}
__device__ __align__(16) float g_gt[9][MGT];

__global__ void gt_pre_kernel(const float* __restrict__ gt) {
    int i = blockIdx.x * blockDim.x + threadIdx.x;
    if (i < MGT) {
        float4 b = reinterpret_cast<const float4*>(gt)[i];
        float x0 = b.x - 0.5f * b.z;
        float y0 = b.y - 0.5f * b.w;
        float x1 = b.x + 0.5f * b.z;
        float y1 = b.y + 0.5f * b.w;
        g_gt[0][i] = b.x;
        g_gt[1][i] = b.y;
        g_gt[2][i] = b.z;
        g_gt[3][i] = b.w;
        g_gt[4][i] = x0;
        g_gt[5][i] = y0;
        g_gt[6][i] = x1;
        g_gt[7][i] = y1;
        g_gt[8][i] = (x1 - x0) * (y1 - y0);
    }
}

// Two gt elements (a,b) against one pred, packed f32x2 arithmetic.
// cost = 5*l1 + 2 - 2*(inter/uni + uni/ea)
//      = 5*l1 + 2 - 2*(inter*ea + uni^2) / (uni*ea)
__device__ __forceinline__ void cost_pair(
    u64 pcx_p, u64 pcy_p, u64 pw_p, u64 ph_p, u64 pa_p,
    float px0, float py0, float px1, float py1,
    u64 gcx_p, u64 gcy_p, u64 gw_p, u64 gh_p, u64 ga_p,
    float gx0a, float gy0a, float gx1a, float gy1a,
    float gx0b, float gy0b, float gx1b, float gy1b,
    u64 cn1, u64 cn2, u64 c5, u64 c2,
    float& ra, float& rb)
{
    // L1: packed diffs (pred - gt), scalar abs-adds (abs folds into FADD)
    u64 dcx = fma2(gcx_p, cn1, pcx_p);
    u64 dcy = fma2(gcy_p, cn1, pcy_p);
    u64 dw  = fma2(gw_p,  cn1, pw_p);
    u64 dh  = fma2(gh_p,  cn1, ph_p);
    float dcxa, dcxb, dcya, dcyb, dwa, dwb, dha, dhb;
    upk(dcx, dcxa, dcxb); upk(dcy, dcya, dcyb);
    upk(dw,  dwa,  dwb ); upk(dh,  dha,  dhb );
    float l1a = (fabsf(dcxa) + fabsf(dcya)) + (fabsf(dwa) + fabsf(dha));
    float l1b = (fabsf(dcxb) + fabsf(dcyb)) + (fabsf(dwb) + fabsf(dhb));
    u64 l1_p = pk(l1a, l1b);

    // Scalar min/max sections (FMNMX on the alu pipe; has headroom)
    float iwa = fmaxf(f_sub(fminf(px1, gx1a), fmaxf(px0, gx0a)), 0.0f);
    float iha = fmaxf(f_sub(fminf(py1, gy1a), fmaxf(py0, gy0a)), 0.0f);
    float intera = iwa * iha;
    float eaa = f_sub(fmaxf(px1, gx1a), fminf(px0, gx0a)) *
                f_sub(fmaxf(py1, gy1a), fminf(py0, gy0a));

    float iwb = fmaxf(f_sub(fminf(px1, gx1b), fmaxf(px0, gx0b)), 0.0f);
    float ihb = fmaxf(f_sub(fminf(py1, gy1b), fmaxf(py0, gy0b)), 0.0f);
    float interb = iwb * ihb;
    float eab = f_sub(fmaxf(px1, gx1b), fminf(px0, gx0b)) *
                f_sub(fmaxf(py1, gy1b), fminf(py0, gy0b));

    // Packed GIoU tail with combined denominator
    u64 inter_p = pk(intera, interb);
    u64 ea_p    = pk(eaa, eab);
    u64 uni_p   = fma2(inter_p, cn1, add2(pa_p, ga_p));   // pa+ga-inter
    u64 m_p     = mul2(uni_p, ea_p);                      // uni*ea
    float m0, m1; upk(m_p, m0, m1);
    u64 r_p  = pk(f_rcp(m0), f_rcp(m1));                  // 2x MUFU.RCP
    u64 nb_p = fma2(uni_p, uni_p, mul2(inter_p, ea_p));   // inter*ea + uni^2
    u64 s_p  = mul2(nb_p, r_p);                           // iou + uea
    u64 t_p  = fma2(l1_p, c5, c2);                        // 5*l1 + 2
    t_p = fma2(s_p, cn2, t_p);                            // - 2*s
    upk(t_p, ra, rb);
}

__global__ void __launch_bounds__(TPB)
cost_kernel(const float* __restrict__ pred, float* __restrict__ out)
{
    int id = blockIdx.x * TPB + threadIdx.x;
    int pg = id / COLS4;
    int c  = id - pg * COLS4;
    int p0 = pg * PPT;

    const u64 cn1 = pk(-1.0f, -1.0f);
    const u64 cn2 = pk(-2.0f, -2.0f);
    const u64 c5  = pk( 5.0f,  5.0f);
    const u64 c2  = pk( 2.0f,  2.0f);

    // 9 coalesced LDG.128 from the hot GT table
    float4 gcx = reinterpret_cast<const float4*>(g_gt[0])[c];
    float4 gcy = reinterpret_cast<const float4*>(g_gt[1])[c];
    float4 gw  = reinterpret_cast<const float4*>(g_gt[2])[c];
    float4 gh  = reinterpret_cast<const float4*>(g_gt[3])[c];
    float4 gx0 = reinterpret_cast<const float4*>(g_gt[4])[c];
    float4 gy0 = reinterpret_cast<const float4*>(g_gt[5])[c];
    float4 gx1 = reinterpret_cast<const float4*>(g_gt[6])[c];
    float4 gy1 = reinterpret_cast<const float4*>(g_gt[7])[c];
    float4 ga  = reinterpret_cast<const float4*>(g_gt[8])[c];

    // GT pairs packed once, reused across PPT preds
    u64 gcx01 = pk(gcx.x, gcx.y), gcx23 = pk(gcx.z, gcx.w);
    u64 gcy01 = pk(gcy.x, gcy.y), gcy23 = pk(gcy.z, gcy.w);
    u64 gw01  = pk(gw.x,  gw.y ), gw23  = pk(gw.z,  gw.w );
    u64 gh01  = pk(gh.x,  gh.y ), gh23  = pk(gh.z,  gh.w );
    u64 ga01  = pk(ga.x,  ga.y ), ga23  = pk(ga.z,  ga.w );

    #pragma unroll
    for (int k = 0; k < PPT; ++k) {
        int p = p0 + k;
        // Pred box: identical address across the warp -> broadcast load
        float4 pb = reinterpret_cast<const float4*>(pred)[p];
        float px0 = fmaf(-0.5f, pb.z, pb.x);
        float py0 = fmaf(-0.5f, pb.w, pb.y);
        float px1 = fmaf( 0.5f, pb.z, pb.x);
        float py1 = fmaf( 0.5f, pb.w, pb.y);
        float pa  = pb.z * pb.w;

        u64 pcx_p = pk(pb.x, pb.x);
        u64 pcy_p = pk(pb.y, pb.y);
        u64 pw_p  = pk(pb.z, pb.z);
        u64 ph_p  = pk(pb.w, pb.w);
        u64 pa_p  = pk(pa,   pa  );

        float4 res;
        cost_pair(pcx_p, pcy_p, pw_p, ph_p, pa_p,
                  px0, py0, px1, py1,
                  gcx01, gcy01, gw01, gh01, ga01,
                  gx0.x, gy0.x, gx1.x, gy1.x,
                  gx0.y, gy0.y, gx1.y, gy1.y,
                  cn1, cn2, c5, c2, res.x, res.y);
        cost_pair(pcx_p, pcy_p, pw_p, ph_p, pa_p,
                  px0, py0, px1, py1,
                  gcx23, gcy23, gw23, gh23, ga23,
                  gx0.z, gy0.z, gx1.z, gy1.z,
                  gx0.w, gy0.w, gx1.w, gy1.w,
                  cn1, cn2, c5, c2, res.z, res.w);

        reinterpret_cast<float4*>(out)[p * COLS4 + c] = res;
    }
}

extern "C" void kernel_launch(void* const* d_in, const int* in_sizes, int n_in,
                              void* d_out, int out_size)
{
    (void)in_sizes; (void)n_in; (void)out_size;
    const float* pred = (const float*)d_in[0];
    const float* gt   = (const float*)d_in[1];
    float* out        = (float*)d_out;

    gt_pre_kernel<<<(MGT + TPB - 1) / TPB, TPB>>>(gt);
    cost_kernel<<<TOTTH / TPB, TPB>>>(pred, out);
}

// round 5
// speedup vs baseline: 1.3380x; 1.0645x over previous
#include <cuda_runtime.h>

// Problem shape (fixed by the dataset):
//   pred_boxes: [16, 900, 4] fp32 (cxcywh)  -> 14400 preds
//   gt_boxes:   [1600, 4]    fp32 (cxcywh)
//   out:        [16, 900, 1600] fp32 cost = 5*L1 - 2*GIoU
#define MGT    1600
#define COLS4  (MGT / 4)            // 400 float4 columns per pred row
#define NPRED  (16 * 900)           // 14400
#define PPT    4                    // preds per thread
#define NGRP   (NPRED / PPT)        // 3600
#define TOTTH  (NGRP * COLS4)       // 1,440,000 threads
#define TPB    256                  // 5625 blocks, exact

typedef unsigned long long u64;     // packed f32x2 (register pair)

// ---- f32x2 packed helpers (sm_100a FFMA2 path) ----
__device__ __forceinline__ u64 pk(float lo, float hi) {
    u64 r; asm("mov.b64 %0, {%1, %2};" : "=l"(r) : "f"(lo), "f"(hi)); return r;
}
__device__ __forceinline__ void upk(u64 v, float& lo, float& hi) {
    asm("mov.b64 {%0, %1}, %2;" : "=f"(lo), "=f"(hi) : "l"(v));
}
__device__ __forceinline__ u64 add2(u64 a, u64 b) {
    u64 d; asm("add.rn.f32x2 %0, %1, %2;" : "=l"(d) : "l"(a), "l"(b)); return d;
}
__device__ __forceinline__ u64 mul2(u64 a, u64 b) {
    u64 d; asm("mul.rn.f32x2 %0, %1, %2;" : "=l"(d) : "l"(a), "l"(b)); return d;
}
__device__ __forceinline__ u64 fma2(u64 a, u64 b, u64 c) {
    u64 d; asm("fma.rn.f32x2 %0, %1, %2, %3;" : "=l"(d) : "l"(a), "l"(b), "l"(c)); return d;
}
__device__ __forceinline__ float f_sub(float a, float b) {          // a - b (FFMA-imm)
    float d; asm("fma.rn.f32 %0, %1, 0fBF800000, %2;" : "=f"(d) : "f"(b), "f"(a)); return d;
}
__device__ __forceinline__ float f_rcp(float a) {                   // MUFU.RCP only
    float d; asm("rcp.approx.f32 %0, %1;" : "=f"(d) : "f"(a)); return d;
}

// GT-derived SoA table: rows = {cx, cy, w, h, x0, y0, x1, y1, area}
__device__ __align__(16) float g_gt[9][MGT];

__global__ void gt_pre_kernel(const float* __restrict__ gt) {
    int i = blockIdx.x * blockDim.x + threadIdx.x;
    if (i < MGT) {
        float4 b = reinterpret_cast<const float4*>(gt)[i];
        float x0 = b.x - 0.5f * b.z;
        float y0 = b.y - 0.5f * b.w;
        float x1 = b.x + 0.5f * b.z;
        float y1 = b.y + 0.5f * b.w;
        g_gt[0][i] = b.x;
        g_gt[1][i] = b.y;
        g_gt[2][i] = b.z;
        g_gt[3][i] = b.w;
        g_gt[4][i] = x0;
        g_gt[5][i] = y0;
        g_gt[6][i] = x1;
        g_gt[7][i] = y1;
        g_gt[8][i] = (x1 - x0) * (y1 - y0);
    }
}

// Two gt elements (a,b) vs one pred, packed f32x2 arithmetic.
// cost = 5*l1 + 2 - 2*(inter*ea + uni^2) / (uni*ea)
// Enclosing box via the exact identity: ew = (pw+gw) - iw_raw, since
// min(a,b)+max(a,b) = a+b  ->  no FMNMX needed for the enclosing box.
__device__ __forceinline__ void cost_pair(
    u64 pcx_p, u64 pcy_p, u64 pw_p, u64 ph_p, u64 pa_p,
    float px0, float py0, float px1, float py1,
    u64 gcx_p, u64 gcy_p, u64 gw_p, u64 gh_p, u64 ga_p,
    float gx0a, float gy0a, float gx1a, float gy1a,
    float gx0b, float gy0b, float gx1b, float gy1b,
    u64 cn1, u64 cn2, u64 c5, u64 c2,
    float& ra, float& rb)
{
    // L1: packed diffs (pred - gt), scalar abs-adds (|src| free on FADD)
    u64 dcx = fma2(gcx_p, cn1, pcx_p);
    u64 dcy = fma2(gcy_p, cn1, pcy_p);
    u64 dw  = fma2(gw_p,  cn1, pw_p);
    u64 dh  = fma2(gh_p,  cn1, ph_p);
    float dcxa, dcxb, dcya, dcyb, dwa, dwb, dha, dhb;
    upk(dcx, dcxa, dcxb); upk(dcy, dcya, dcyb);
    upk(dw,  dwa,  dwb ); upk(dh,  dha,  dhb );
    float l1a = (fabsf(dcxa) + fabsf(dcya)) + (fabsf(dwa) + fabsf(dha));
    float l1b = (fabsf(dcxb) + fabsf(dcyb)) + (fabsf(dwb) + fabsf(dhb));
    u64 l1_p = pk(l1a, l1b);

    // Intersection raw widths (scalar FMNMX on alu pipe)
    float iwra = f_sub(fminf(px1, gx1a), fmaxf(px0, gx0a));
    float ihra = f_sub(fminf(py1, gy1a), fmaxf(py0, gy0a));
    float iwrb = f_sub(fminf(px1, gx1b), fmaxf(px0, gx0b));
    float ihrb = f_sub(fminf(py1, gy1b), fmaxf(py0, gy0b));

    float intera = fmaxf(iwra, 0.0f) * fmaxf(ihra, 0.0f);
    float interb = fmaxf(iwrb, 0.0f) * fmaxf(ihrb, 0.0f);

    // Enclosing box via identity, fully packed on the fma pipe
    u64 iwr_p = pk(iwra, iwrb);
    u64 ihr_p = pk(ihra, ihrb);
    u64 pwgw  = add2(pw_p, gw_p);
    u64 phgh  = add2(ph_p, gh_p);
    u64 ew_p  = fma2(iwr_p, cn1, pwgw);    // (pw+gw) - iw_raw
    u64 eh_p  = fma2(ihr_p, cn1, phgh);    // (ph+gh) - ih_raw
    u64 ea_p  = mul2(ew_p, eh_p);

    // Packed GIoU tail with combined denominator
    u64 inter_p = pk(intera, interb);
    u64 uni_p   = fma2(inter_p, cn1, add2(pa_p, ga_p));   // pa+ga-inter
    u64 m_p     = mul2(uni_p, ea_p);                      // uni*ea
    float m0, m1; upk(m_p, m0, m1);
    u64 r_p  = pk(f_rcp(m0), f_rcp(m1));                  // 2x MUFU.RCP
    u64 nb_p = fma2(uni_p, uni_p, mul2(inter_p, ea_p));   // inter*ea + uni^2
    u64 s_p  = mul2(nb_p, r_p);                           // iou + uni/ea
    u64 t_p  = fma2(l1_p, c5, c2);                        // 5*l1 + 2
    t_p = fma2(s_p, cn2, t_p);                            // - 2*s
    upk(t_p, ra, rb);
}

__global__ void __launch_bounds__(TPB)
cost_kernel(const float* __restrict__ pred, float* __restrict__ out)
{
    int id = blockIdx.x * TPB + threadIdx.x;
    int pg = id / COLS4;
    int c  = id - pg * COLS4;
    int p0 = pg * PPT;

    const u64 cn1 = pk(-1.0f, -1.0f);
    const u64 cn2 = pk(-2.0f, -2.0f);
    const u64 c5  = pk( 5.0f,  5.0f);
    const u64 c2  = pk( 2.0f,  2.0f);

    // 9 coalesced LDG.128 from the hot GT table
    float4 gcx = reinterpret_cast<const float4*>(g_gt[0])[c];
    float4 gcy = reinterpret_cast<const float4*>(g_gt[1])[c];
    float4 gw  = reinterpret_cast<const float4*>(g_gt[2])[c];
    float4 gh  = reinterpret_cast<const float4*>(g_gt[3])[c];
    float4 gx0 = reinterpret_cast<const float4*>(g_gt[4])[c];
    float4 gy0 = reinterpret_cast<const float4*>(g_gt[5])[c];
    float4 gx1 = reinterpret_cast<const float4*>(g_gt[6])[c];
    float4 gy1 = reinterpret_cast<const float4*>(g_gt[7])[c];
    float4 ga  = reinterpret_cast<const float4*>(g_gt[8])[c];

    // GT pairs packed once, reused across PPT preds
    u64 gcx01 = pk(gcx.x, gcx.y), gcx23 = pk(gcx.z, gcx.w);
    u64 gcy01 = pk(gcy.x, gcy.y), gcy23 = pk(gcy.z, gcy.w);
    u64 gw01  = pk(gw.x,  gw.y ), gw23  = pk(gw.z,  gw.w );
    u64 gh01  = pk(gh.x,  gh.y ), gh23  = pk(gh.z,  gh.w );
    u64 ga01  = pk(ga.x,  ga.y ), ga23  = pk(ga.z,  ga.w );

    #pragma unroll
    for (int k = 0; k < PPT; ++k) {
        int p = p0 + k;
        // Pred box: identical address across the warp -> broadcast load
        float4 pb = reinterpret_cast<const float4*>(pred)[p];
        float px0 = fmaf(-0.5f, pb.z, pb.x);
        float py0 = fmaf(-0.5f, pb.w, pb.y);
        float px1 = fmaf( 0.5f, pb.z, pb.x);
        float py1 = fmaf( 0.5f, pb.w, pb.y);
        float pa  = pb.z * pb.w;

        u64 pcx_p = pk(pb.x, pb.x);
        u64 pcy_p = pk(pb.y, pb.y);
        u64 pw_p  = pk(pb.z, pb.z);
        u64 ph_p  = pk(pb.w, pb.w);
        u64 pa_p  = pk(pa,   pa  );

        float4 res;
        cost_pair(pcx_p, pcy_p, pw_p, ph_p, pa_p,
                  px0, py0, px1, py1,
                  gcx01, gcy01, gw01, gh01, ga01,
                  gx0.x, gy0.x, gx1.x, gy1.x,
                  gx0.y, gy0.y, gx1.y, gy1.y,
                  cn1, cn2, c5, c2, res.x, res.y);
        cost_pair(pcx_p, pcy_p, pw_p, ph_p, pa_p,
                  px0, py0, px1, py1,
                  gcx23, gcy23, gw23, gh23, ga23,
                  gx0.z, gy0.z, gx1.z, gy1.z,
                  gx0.w, gy0.w, gx1.w, gy1.w,
                  cn1, cn2, c5, c2, res.z, res.w);

        reinterpret_cast<float4*>(out)[p * COLS4 + c] = res;
    }
}

extern "C" void kernel_launch(void* const* d_in, const int* in_sizes, int n_in,
                              void* d_out, int out_size)
{
    (void)in_sizes; (void)n_in; (void)out_size;
    const float* pred = (const float*)d_in[0];
    const float* gt   = (const float*)d_in[1];
    float* out        = (float*)d_out;

    gt_pre_kernel<<<(MGT + TPB - 1) / TPB, TPB>>>(gt);
    cost_kernel<<<TOTTH / TPB, TPB>>>(pred, out);
}

// round 7
// speedup vs baseline: 1.5000x; 1.1211x over previous
#include <cuda_runtime.h>

// Problem shape (fixed by the dataset):
//   pred_boxes: [16, 900, 4] fp32 (cxcywh)  -> 14400 preds
//   gt_boxes:   [1600, 4]    fp32 (cxcywh)
//   out:        [16, 900, 1600] fp32 cost = 5*L1 - 2*GIoU
#define MGT    1600
#define COLS4  (MGT / 4)            // 400 float4 columns per pred row
#define NPRED  (16 * 900)           // 14400
#define PPT    4                    // preds per thread
#define NGRP   (NPRED / PPT)        // 3600
#define TOTTH  (NGRP * COLS4)       // 1,440,000 threads
#define TPB    256                  // 5625 blocks, exact

typedef unsigned long long u64;     // packed f32x2 (register pair)

// ---- f32x2 packed helpers ----
__device__ __forceinline__ u64 pk(float lo, float hi) {
    u64 r; asm("mov.b64 %0, {%1, %2};" : "=l"(r) : "f"(lo), "f"(hi)); return r;
}
__device__ __forceinline__ void upk(u64 v, float& lo, float& hi) {
    asm("mov.b64 {%0, %1}, %2;" : "=f"(lo), "=f"(hi) : "l"(v));
}
__device__ __forceinline__ u64 add2(u64 a, u64 b) {
    u64 d; asm("add.rn.f32x2 %0, %1, %2;" : "=l"(d) : "l"(a), "l"(b)); return d;
}
__device__ __forceinline__ u64 mul2(u64 a, u64 b) {
    u64 d; asm("mul.rn.f32x2 %0, %1, %2;" : "=l"(d) : "l"(a), "l"(b)); return d;
}
__device__ __forceinline__ u64 fma2(u64 a, u64 b, u64 c) {
    u64 d; asm("fma.rn.f32x2 %0, %1, %2, %3;" : "=l"(d) : "l"(a), "l"(b), "l"(c)); return d;
}
__device__ __forceinline__ float f_rcp(float a) {                   // MUFU.RCP only
    float d; asm("rcp.approx.f32 %0, %1;" : "=f"(d) : "f"(a)); return d;
}

// GT-derived SoA table: rows = {cx, cy, 0.5*w, 0.5*h, area}
__device__ __align__(16) float g_gt[5][MGT];

__global__ void gt_pre_kernel(const float* __restrict__ gt) {
    int i = blockIdx.x * blockDim.x + threadIdx.x;
    if (i < MGT) {
        float4 b = reinterpret_cast<const float4*>(gt)[i];
        g_gt[0][i] = b.x;
        g_gt[1][i] = b.y;
        g_gt[2][i] = 0.5f * b.z;
        g_gt[3][i] = 0.5f * b.w;
        g_gt[4][i] = b.z * b.w;
    }
}

// Two gt elements (lanes a,b) vs one pred.
// Correct interval identities (d = center diff, s = sum of half-widths,
// dwh = half-width diff):
//   iw_raw = s - max(|d|, |dwh|)
//   ew     = s + max(|d|, |dwh|)
//   l1 = |dcx|+|dcy| + 2*(|dwh|+|dhh|)
//   cost = 5*l1 + 2 - 2*(inter*ea + uni^2)/(uni*ea)
__device__ __forceinline__ void cost_pair(
    u64 pcx_p, u64 pcy_p, u64 pwh_p, u64 phh_p, u64 pa_p,
    u64 gcx_p, u64 gcy_p, u64 ghw_p, u64 ghh_p, u64 ga_p,
    u64 cn1, u64 cn2, u64 c5, u64 c2,
    float& ra, float& rb)
{
    // Packed diffs and half-width sums (fma pipe, 6 slots)
    u64 dcx_p = fma2(gcx_p, cn1, pcx_p);
    u64 dcy_p = fma2(gcy_p, cn1, pcy_p);
    u64 dwh_p = fma2(ghw_p, cn1, pwh_p);
    u64 dhh_p = fma2(ghh_p, cn1, phh_p);
    u64 sx_p  = add2(ghw_p, pwh_p);
    u64 sy_p  = add2(ghh_p, phh_p);

    float dcxa, dcxb, dcya, dcyb, dwha, dwhb, dhha, dhhb, sxa, sxb, sya, syb;
    upk(dcx_p, dcxa, dcxb); upk(dcy_p, dcya, dcyb);
    upk(dwh_p, dwha, dwhb); upk(dhh_p, dhha, dhhb);
    upk(sx_p,  sxa,  sxb ); upk(sy_p,  sya,  syb );

    // Scalar sections in plain C so ptxas folds |src| into FADD/FMNMX
    // L1 (3 ops/lane)
    float l1a = fmaf(2.0f, fabsf(dwha) + fabsf(dhha), fabsf(dcxa) + fabsf(dcya));
    float l1b = fmaf(2.0f, fabsf(dwhb) + fabsf(dhhb), fabsf(dcxb) + fabsf(dcyb));

    // Geometry via CORRECT identity: mx = max(|d|,|dwh|) per axis
    float mxxa = fmaxf(fabsf(dcxa), fabsf(dwha));
    float mxya = fmaxf(fabsf(dcya), fabsf(dhha));
    float iwa = fmaxf(sxa - mxxa, 0.0f);
    float iha = fmaxf(sya - mxya, 0.0f);
    float intera = iwa * iha;
    float eaa = (sxa + mxxa) * (sya + mxya);

    float mxxb = fmaxf(fabsf(dcxb), fabsf(dwhb));
    float mxyb = fmaxf(fabsf(dcyb), fabsf(dhhb));
    float iwb = fmaxf(sxb - mxxb, 0.0f);
    float ihb = fmaxf(syb - mxyb, 0.0f);
    float interb = iwb * ihb;
    float eab = (sxb + mxxb) * (syb + mxyb);

    // Packed GIoU tail with combined denominator
    u64 inter_p = pk(intera, interb);
    u64 ea_p    = pk(eaa, eab);
    u64 l1_p    = pk(l1a, l1b);
    u64 uni_p   = fma2(inter_p, cn1, add2(pa_p, ga_p));   // pa+ga-inter
    u64 m_p     = mul2(uni_p, ea_p);                      // uni*ea
    float m0, m1; upk(m_p, m0, m1);
    u64 r_p  = pk(f_rcp(m0), f_rcp(m1));                  // 2x MUFU.RCP
    u64 nb_p = fma2(uni_p, uni_p, mul2(inter_p, ea_p));   // inter*ea + uni^2
    u64 s_p  = mul2(nb_p, r_p);                           // iou + uni/ea
    u64 t_p  = fma2(l1_p, c5, c2);                        // 5*l1 + 2
    t_p = fma2(s_p, cn2, t_p);                            // - 2*s
    upk(t_p, ra, rb);
}

__global__ void __launch_bounds__(TPB)
cost_kernel(const float* __restrict__ pred, float* __restrict__ out)
{
    int id = blockIdx.x * TPB + threadIdx.x;
    int pg = id / COLS4;
    int c  = id - pg * COLS4;
    int p0 = pg * PPT;

    const u64 cn1 = pk(-1.0f, -1.0f);
    const u64 cn2 = pk(-2.0f, -2.0f);
    const u64 c5  = pk( 5.0f,  5.0f);
    const u64 c2  = pk( 2.0f,  2.0f);

    // 5 coalesced LDG.128 from the hot GT table
    float4 gcx = reinterpret_cast<const float4*>(g_gt[0])[c];
    float4 gcy = reinterpret_cast<const float4*>(g_gt[1])[c];
    float4 ghw = reinterpret_cast<const float4*>(g_gt[2])[c];
    float4 ghh = reinterpret_cast<const float4*>(g_gt[3])[c];
    float4 ga  = reinterpret_cast<const float4*>(g_gt[4])[c];

    // GT pairs packed once, reused across PPT preds
    u64 gcx01 = pk(gcx.x, gcx.y), gcx23 = pk(gcx.z, gcx.w);
    u64 gcy01 = pk(gcy.x, gcy.y), gcy23 = pk(gcy.z, gcy.w);
    u64 ghw01 = pk(ghw.x, ghw.y), ghw23 = pk(ghw.z, ghw.w);
    u64 ghh01 = pk(ghh.x, ghh.y), ghh23 = pk(ghh.z, ghh.w);
    u64 ga01  = pk(ga.x,  ga.y ), ga23  = pk(ga.z,  ga.w );

    #pragma unroll
    for (int k = 0; k < PPT; ++k) {
        int p = p0 + k;
        // Pred box: identical address across the warp -> broadcast load
        float4 pb = reinterpret_cast<const float4*>(pred)[p];
        float pwh = 0.5f * pb.z;
        float phh = 0.5f * pb.w;
        float pa  = pb.z * pb.w;

        u64 pcx_p = pk(pb.x, pb.x);
        u64 pcy_p = pk(pb.y, pb.y);
        u64 pwh_p = pk(pwh,  pwh);
        u64 phh_p = pk(phh,  phh);
        u64 pa_p  = pk(pa,   pa );

        float4 res;
        cost_pair(pcx_p, pcy_p, pwh_p, phh_p, pa_p,
                  gcx01, gcy01, ghw01, ghh01, ga01,
                  cn1, cn2, c5, c2, res.x, res.y);
        cost_pair(pcx_p, pcy_p, pwh_p, phh_p, pa_p,
                  gcx23, gcy23, ghw23, ghh23, ga23,
                  cn1, cn2, c5, c2, res.z, res.w);

        reinterpret_cast<float4*>(out)[p * COLS4 + c] = res;
    }
}

extern "C" void kernel_launch(void* const* d_in, const int* in_sizes, int n_in,
                              void* d_out, int out_size)
{
    (void)in_sizes; (void)n_in; (void)out_size;
    const float* pred = (const float*)d_in[0];
    const float* gt   = (const float*)d_in[1];
    float* out        = (float*)d_out;

    gt_pre_kernel<<<(MGT + TPB - 1) / TPB, TPB>>>(gt);
    cost_kernel<<<TOTTH / TPB, TPB>>>(pred, out);
}